// round 10
// baseline (speedup 1.0000x reference)
#include <cuda_runtime.h>
#include <stdint.h>

#define BATCH 64
#define INSZ 1024
#define KSZ 1025          // inputs + bias neuron (bias always first: t=1.0 <= X)
#define KPAD 1056         // 66 chunks of 16 (padding: w=0, dx=0 -> provable no-op)
#define CHUNK 16
#define NCHUNK (KPAD / CHUNK)
#define NSTAGE 4
#define MSZ 1024
#define COLS_PER_CTA 512
#define THREADS 256
#define MAX_SPIKE 100000.0f

// dynamic smem layout (bytes)
#define SB_STAGE (NSTAGE * CHUNK * COLS_PER_CTA * 4)   // 131072
#define SB_DX2   (KPAD * 8)                            // 8448
#define SB_ROW   (KPAD * 4)                            // 4224
#define SMEM_BYTES (SB_STAGE + SB_DX2 + SB_ROW)        // 143744

// Scratch: per batch, sorted spike times, duplicated gaps, W-row byte offsets.
__device__ float  g_xs[BATCH][KPAD];
__device__ float2 g_dx2[BATCH][KPAD];
__device__ int    g_row[BATCH][KPAD];

// ---- packed f32x2 helpers (Blackwell FFMA2/FADD2, rn non-ftz) -------------
__device__ __forceinline__ unsigned long long add2(unsigned long long a,
                                                   unsigned long long b) {
    unsigned long long d;
    asm("add.rn.f32x2 %0, %1, %2;" : "=l"(d) : "l"(a), "l"(b));
    return d;
}
__device__ __forceinline__ unsigned long long fma2(unsigned long long a,
                                                   unsigned long long b,
                                                   unsigned long long c) {
    unsigned long long d;
    asm("fma.rn.f32x2 %0, %1, %2, %3;" : "=l"(d) : "l"(a), "l"(b), "l"(c));
    return d;
}
__device__ __forceinline__ float lo2(unsigned long long v) {
    return __uint_as_float((unsigned)v);
}
__device__ __forceinline__ float hi2(unsigned long long v) {
    return __uint_as_float((unsigned)(v >> 32));
}
__device__ __forceinline__ unsigned long long pack2(float a, float b) {
    unsigned long long r;
    asm("mov.b64 %0, {%1, %2};" : "=l"(r) : "f"(a), "f"(b));
    return r;
}
// exact-rounding scalars for the replay (bit-identical to the f32x2 lanes)
__device__ __forceinline__ float fadd_rn(float a, float b) {
    float d; asm("add.rn.f32 %0, %1, %2;" : "=f"(d) : "f"(a), "f"(b)); return d;
}
__device__ __forceinline__ float ffma_rn(float a, float b, float c) {
    float d; asm("fma.rn.f32 %0, %1, %2, %3;" : "=f"(d) : "f"(a), "f"(b), "f"(c)); return d;
}

// ---------------------------------------------------------------------------
// Kernel 1: per-batch bitonic sort of the 1024 X values (bias hardcoded at
// slot 0 since bias=1.0 <= min X; tie order provably irrelevant).
// ---------------------------------------------------------------------------
__global__ void __launch_bounds__(1024) snn_sort_kernel(const float* __restrict__ X) {
    __shared__ unsigned long long sh[1024];
    __shared__ float sx[1025];
    const int b = blockIdx.x;
    const int t = threadIdx.x;

    unsigned long long v =
        ((unsigned long long)__float_as_uint(X[b * INSZ + t]) << 32) | (unsigned)t;

    #pragma unroll 1
    for (int size = 2; size <= 1024; size <<= 1) {
        #pragma unroll 1
        for (int stride = size >> 1; stride >= 32; stride >>= 1) {
            sh[t] = v;
            __syncthreads();
            const unsigned long long u = sh[t ^ stride];
            __syncthreads();
            const bool dir = (t & size) != 0;
            const bool keepmin = (((t & stride) == 0) != dir);
            v = keepmin ? (v < u ? v : u) : (v < u ? u : v);
        }
        const int s0 = (size >> 1) < 16 ? (size >> 1) : 16;
        #pragma unroll 1
        for (int stride = s0; stride >= 1; stride >>= 1) {
            const unsigned long long u = __shfl_xor_sync(0xffffffffu, v, stride);
            const bool dir = (t & size) != 0;
            const bool keepmin = (((t & stride) == 0) != dir);
            v = keepmin ? (v < u ? v : u) : (v < u ? u : v);
        }
    }

    sx[t + 1] = __uint_as_float((unsigned)(v >> 32));
    if (t == 0) sx[0] = 1.0f;
    __syncthreads();

    const int row = (int)(v & 0xffffffffu);
    const int s = t + 1;
    const float x  = sx[s];
    const float xn = (s == KSZ - 1) ? MAX_SPIKE : sx[s + 1];
    const float dx = xn - x;
    g_xs[b][s]   = x;
    g_dx2[b][s]  = make_float2(dx, dx);
    g_row[b][s]  = row * (MSZ * 4);
    if (t == 0) {
        const float dx0 = sx[1] - 1.0f;
        g_xs[b][0]  = 1.0f;
        g_dx2[b][0] = make_float2(dx0, dx0);
        g_row[b][0] = INSZ * (MSZ * 4);
    }
    if (t < KPAD - KSZ) {   // padding: w-row = bias row (all zeros), dx = 0
        g_xs[b][KSZ + t]  = MAX_SPIKE;
        g_dx2[b][KSZ + t] = make_float2(0.0f, 0.0f);
        g_row[b][KSZ + t] = INSZ * (MSZ * 4);
    }
}

// ---------------------------------------------------------------------------
// Kernel 2: packed-f32x2 margin scan, 2 output columns per thread.
//   cwp_k = cw_k - 1;  G_{k+1} = G_k + cwp_k * dx_k   (G_0 = -x_0 = -1)
// Mainloop tracks only nd = "no crossing yet" per column, plus a per-chunk
// checkpoint (G, cwp, chunk) saved while nd. The crossing chunk is replayed
// (<=16 elements, bit-exact rn arithmetic) at the end to recover the answer:
//   T = x_kf - G_kf / cwp_kf.
// Grid: (MSZ/512, BATCH), 256 threads, 140KB dynamic smem, 4-stage cp.async.
// ---------------------------------------------------------------------------
__global__ void __launch_bounds__(THREADS) snn_scan_kernel(
    const float* __restrict__ W, float* __restrict__ out)
{
    extern __shared__ char smem[];
    float*  sbuf  = (float*)smem;                        // stages
    float2* s_dx2 = (float2*)(smem + SB_STAGE);
    int*    s_row = (int*)(smem + SB_STAGE + SB_DX2);

    const int b = blockIdx.y;
    const int t = threadIdx.x;
    const int mblock = blockIdx.x * COLS_PER_CTA;
    const char* Wcol = (const char*)W + (size_t)mblock * 4;

    for (int i = t; i < KPAD; i += THREADS) {
        s_dx2[i] = g_dx2[b][i];
        s_row[i] = g_row[b][i];
    }
    __syncthreads();

    // issue one chunk: 16 rows x 2KB = 32KB, 8 x 16B cp.async per thread
    auto issue_chunk = [&](int c) {
        const int kb = c * CHUNK;
        float* dstbase = sbuf + (c & (NSTAGE - 1)) * (CHUNK * COLS_PER_CTA);
        #pragma unroll
        for (int i = 0; i < 8; i++) {
            const int lin = i * THREADS + t;
            const int r   = lin >> 7;           // row within chunk (0..15)
            const int seg = lin & 127;          // 16B segment within 2KB row
            const char* src = Wcol + s_row[kb + r] + seg * 16;
            unsigned dsts = (unsigned)__cvta_generic_to_shared(
                dstbase + r * COLS_PER_CTA + seg * 4);
            asm volatile("cp.async.cg.shared.global [%0], [%1], 16;\n"
                         :: "r"(dsts), "l"(src));
        }
        asm volatile("cp.async.commit_group;\n");
    };

    issue_chunk(0);
    issue_chunk(1);
    issue_chunk(2);

    unsigned long long cwp2 = pack2(-1.0f, -1.0f);   // cw - THRESHOLD
    unsigned long long G2   = pack2(-1.0f, -1.0f);   // G_0 = -x_0 = -1
    bool  nd0 = true, nd1 = true;
    float Gc0 = -1.0f, cc0 = -1.0f, Gc1 = -1.0f, cc1 = -1.0f;
    int   cb0 = 0, cb1 = 0;

    #pragma unroll 1
    for (int c = 0; c < NCHUNK; c++) {
        asm volatile("cp.async.wait_group 2;\n");
        __syncthreads();
        // per-chunk checkpoint while not done
        Gc0 = nd0 ? lo2(G2)   : Gc0;
        cc0 = nd0 ? lo2(cwp2) : cc0;
        cb0 = nd0 ? c         : cb0;
        Gc1 = nd1 ? hi2(G2)   : Gc1;
        cc1 = nd1 ? hi2(cwp2) : cc1;
        cb1 = nd1 ? c         : cb1;

        const float* buf = sbuf + (c & (NSTAGE - 1)) * (CHUNK * COLS_PER_CTA);
        const int kb = c * CHUNK;
        #pragma unroll
        for (int u = 0; u < CHUNK; u++) {
            const unsigned long long w2 =
                *(const unsigned long long*)(buf + u * COLS_PER_CTA + 2 * t);
            const unsigned long long dx2 =
                *(const unsigned long long*)(s_dx2 + kb + u);   // broadcast
            cwp2 = add2(cwp2, w2);
            const unsigned long long Gn2 = fma2(cwp2, dx2, G2);
            nd0 = nd0 & (lo2(Gn2) < 0.0f);
            nd1 = nd1 & (hi2(Gn2) < 0.0f);
            G2 = Gn2;
        }
        if (c + 3 < NCHUNK) issue_chunk(c + 3);
        else asm volatile("cp.async.commit_group;\n");   // keep group count
    }

    // replay the crossing chunk for one column (bit-exact rn arithmetic)
    auto replay = [&](int cb, float Gc, float cc, int colbyte) -> float {
        const int kb = cb * CHUNK;
        float warr[CHUNK];
        #pragma unroll
        for (int j = 0; j < CHUNK; j++)
            warr[j] = *(const float*)((const char*)W + s_row[kb + j] + colbyte);
        float G = Gc, cwp = cc, r = MAX_SPIKE;
        bool found = false;
        #pragma unroll
        for (int j = 0; j < CHUNK; j++) {
            const float cn = fadd_rn(cwp, warr[j]);
            const float dx = s_dx2[kb + j].x;
            const float Gn = ffma_rn(cn, dx, G);
            if (!found && Gn >= 0.0f) {
                r = g_xs[b][kb + j] - G / cn;
                found = true;
            }
            cwp = cn; G = Gn;
        }
        return r;
    };

    const int col0 = mblock + 2 * t;
    const float r0 = nd0 ? MAX_SPIKE : replay(cb0, Gc0, cc0, col0 * 4);
    const float r1 = nd1 ? MAX_SPIKE : replay(cb1, Gc1, cc1, (col0 + 1) * 4);
    *(float2*)&out[(size_t)b * MSZ + col0] = make_float2(r0, r1);
}

// ---------------------------------------------------------------------------
extern "C" void kernel_launch(void* const* d_in, const int* in_sizes, int n_in,
                              void* d_out, int out_size) {
    const float* X = (const float*)d_in[0];   // [64, 1024] spike times
    const float* W = (const float*)d_in[1];   // [1025, 1024] weights
    float* out = (float*)d_out;               // [64, 1024]

    cudaFuncSetAttribute(snn_scan_kernel,
                         cudaFuncAttributeMaxDynamicSharedMemorySize, SMEM_BYTES);

    snn_sort_kernel<<<BATCH, 1024>>>(X);
    snn_scan_kernel<<<dim3(MSZ / COLS_PER_CTA, BATCH), THREADS, SMEM_BYTES>>>(W, out);
}

// round 13
// speedup vs baseline: 1.1245x; 1.1245x over previous
#include <cuda_runtime.h>
#include <stdint.h>

#define BATCH 64
#define INSZ 1024
#define KSZ 1025          // inputs + bias neuron (bias always first: t=1.0 <= X)
#define KPAD 1056         // 66 chunks of 16 (padding: w=0, dx=0 -> provable no-op)
#define CHUNK 16
#define NCHUNK (KPAD / CHUNK)
#define NSTAGE 4
#define MSZ 1024
#define MAX_SPIKE 100000.0f

// Scratch: per batch, sorted spike times, gaps, and W-row byte offsets.
__device__ float g_xs[BATCH][KPAD];
__device__ float g_dx[BATCH][KPAD];
__device__ int   g_row[BATCH][KPAD];

// exact-rounding scalars so the replay is bit-identical to the mainloop
__device__ __forceinline__ float fadd_rn(float a, float b) {
    float d; asm("add.rn.f32 %0, %1, %2;" : "=f"(d) : "f"(a), "f"(b)); return d;
}
__device__ __forceinline__ float ffma_rn(float a, float b, float c) {
    float d; asm("fma.rn.f32 %0, %1, %2, %3;" : "=f"(d) : "f"(a), "f"(b), "f"(c)); return d;
}

// ---------------------------------------------------------------------------
// Kernel 1: per-batch bitonic sort of the 1024 X values (bias hardcoded at
// slot 0 since bias=1.0 <= min X; tie order provably irrelevant). Strides <=16
// in registers via shfl_xor; strides >=32 via shared memory.
// ---------------------------------------------------------------------------
__global__ void __launch_bounds__(1024) snn_sort_kernel(const float* __restrict__ X) {
    __shared__ unsigned long long sh[1024];
    __shared__ float sx[1025];
    const int b = blockIdx.x;
    const int t = threadIdx.x;

    unsigned long long v =
        ((unsigned long long)__float_as_uint(X[b * INSZ + t]) << 32) | (unsigned)t;

    #pragma unroll 1
    for (int size = 2; size <= 1024; size <<= 1) {
        #pragma unroll 1
        for (int stride = size >> 1; stride >= 32; stride >>= 1) {
            sh[t] = v;
            __syncthreads();
            const unsigned long long u = sh[t ^ stride];
            __syncthreads();
            const bool dir = (t & size) != 0;
            const bool keepmin = (((t & stride) == 0) != dir);
            v = keepmin ? (v < u ? v : u) : (v < u ? u : v);
        }
        const int s0 = (size >> 1) < 16 ? (size >> 1) : 16;
        #pragma unroll 1
        for (int stride = s0; stride >= 1; stride >>= 1) {
            const unsigned long long u = __shfl_xor_sync(0xffffffffu, v, stride);
            const bool dir = (t & size) != 0;
            const bool keepmin = (((t & stride) == 0) != dir);
            v = keepmin ? (v < u ? v : u) : (v < u ? u : v);
        }
    }

    sx[t + 1] = __uint_as_float((unsigned)(v >> 32));
    if (t == 0) sx[0] = 1.0f;
    __syncthreads();

    const int row = (int)(v & 0xffffffffu);
    const int s = t + 1;
    const float x  = sx[s];
    const float xn = (s == KSZ - 1) ? MAX_SPIKE : sx[s + 1];
    g_xs[b][s]  = x;
    g_dx[b][s]  = xn - x;
    g_row[b][s] = row * (MSZ * 4);
    if (t == 0) {
        g_xs[b][0]  = 1.0f;
        g_dx[b][0]  = sx[1] - 1.0f;
        g_row[b][0] = INSZ * (MSZ * 4);
    }
    if (t < KPAD - KSZ) {   // padding: w-row = bias row (all zeros), dx = 0
        g_xs[b][KSZ + t]  = MAX_SPIKE;
        g_dx[b][KSZ + t]  = 0.0f;
        g_row[b][KSZ + t] = INSZ * (MSZ * 4);
    }
}

// ---------------------------------------------------------------------------
// Kernel 2: margin scan, 1 column/thread, cp.async pipeline + chunk replay.
//   cwp_k = cw_k - 1;  G_{k+1} = G_k + cwp_k * dx_k   (G_0 = -x_0 = -1)
// Mainloop per element: LDS w, LDS dx, FADD, FFMA, FSETP (nd &&= Gn<0).
// Per chunk: checkpoint (G, cwp, chunk#) while nd. The crossing chunk is
// replayed afterwards (<=16 elements, bit-exact rn ops, W via L2-hot LDG):
//   T = x_kf - G_kf / cwp_kf.
// Grid: (MSZ/128, BATCH), 128 threads.
// ---------------------------------------------------------------------------
__global__ void __launch_bounds__(128) snn_scan_kernel(
    const float* __restrict__ W, float* __restrict__ out)
{
    __shared__ float sbuf[NSTAGE][CHUNK * 128];   // 32 KB
    __shared__ float s_dx[KPAD];
    __shared__ int   s_row[KPAD];

    const int b = blockIdx.y;
    const int t = threadIdx.x;
    const int mblock = blockIdx.x * 128;
    const char* Wcol = (const char*)W + (size_t)mblock * 4;

    for (int i = t; i < KPAD; i += 128) {
        s_dx[i]  = g_dx[b][i];
        s_row[i] = g_row[b][i];
    }
    __syncthreads();

    // issue one chunk: 16 rows x 512B = 8KB, 4 x 16B cp.async per thread
    auto issue_chunk = [&](int c) {
        const int kb = c * CHUNK;
        float* dstbase = sbuf[c & (NSTAGE - 1)];
        #pragma unroll
        for (int i = 0; i < 4; i++) {
            const int lin = i * 128 + t;
            const int r   = lin >> 5;          // row within chunk (0..15)
            const int seg = lin & 31;          // 16B segment within 512B row slice
            const char* src = Wcol + s_row[kb + r] + seg * 16;
            unsigned dsts = (unsigned)__cvta_generic_to_shared(dstbase + r * 128 + seg * 4);
            asm volatile("cp.async.cg.shared.global [%0], [%1], 16;\n"
                         :: "r"(dsts), "l"(src));
        }
        asm volatile("cp.async.commit_group;\n");
    };

    issue_chunk(0);
    issue_chunk(1);
    issue_chunk(2);

    float cwp = -1.0f;          // cw - THRESHOLD
    float G   = -1.0f;          // G_0 = -x_0, x_0 = bias = 1.0
    bool  nd  = true;           // not done (no crossing yet)
    float Gc  = -1.0f, cc = -1.0f;
    int   cb  = 0;

    #pragma unroll 1
    for (int c = 0; c < NCHUNK; c++) {
        asm volatile("cp.async.wait_group 2;\n");
        __syncthreads();
        // per-chunk checkpoint while not done
        Gc = nd ? G   : Gc;
        cc = nd ? cwp : cc;
        cb = nd ? c   : cb;

        const float* buf = sbuf[c & (NSTAGE - 1)];
        const int kb = c * CHUNK;
        #pragma unroll
        for (int u = 0; u < CHUNK; u++) {
            const float w  = buf[u * 128 + t];
            const float dx = s_dx[kb + u];
            cwp = fadd_rn(cwp, w);
            const float Gn = ffma_rn(cwp, dx, G);
            nd = nd && (Gn < 0.0f);
            G  = Gn;
        }
        if (c + 3 < NCHUNK) issue_chunk(c + 3);
        else asm volatile("cp.async.commit_group;\n");   // keep group count
    }

    // replay the crossing chunk (bit-exact rn arithmetic, W via L2-hot LDG)
    float res = MAX_SPIKE;
    if (!nd) {
        const int kb = cb * CHUNK;
        const int colbyte = (mblock + t) * 4;
        float Gr = Gc, cr = cc;
        bool found = false;
        #pragma unroll
        for (int j = 0; j < CHUNK; j++) {
            const float w  = *(const float*)((const char*)W + s_row[kb + j] + colbyte);
            const float cn = fadd_rn(cr, w);
            const float Gn = ffma_rn(cn, s_dx[kb + j], Gr);
            if (!found && Gn >= 0.0f) {
                res = g_xs[b][kb + j] - Gr / cn;
                found = true;
            }
            cr = cn; Gr = Gn;
        }
    }
    out[(size_t)b * MSZ + mblock + t] = res;
}

// ---------------------------------------------------------------------------
extern "C" void kernel_launch(void* const* d_in, const int* in_sizes, int n_in,
                              void* d_out, int out_size) {
    const float* X = (const float*)d_in[0];   // [64, 1024] spike times
    const float* W = (const float*)d_in[1];   // [1025, 1024] weights
    float* out = (float*)d_out;               // [64, 1024]

    snn_sort_kernel<<<BATCH, 1024>>>(X);
    snn_scan_kernel<<<dim3(MSZ / 128, BATCH), 128>>>(W, out);
}

// round 14
// speedup vs baseline: 1.3275x; 1.1806x over previous
#include <cuda_runtime.h>
#include <stdint.h>

#define BATCH 64
#define INSZ 1024
#define KSZ 1025          // inputs + bias neuron (bias always first: t=1.0 <= X)
#define KPAD 1056         // 132 chunks of 8 (padding: w=0, dx=0 -> provable no-op)
#define CHUNK 8
#define NCHUNK (KPAD / CHUNK)   // 132
#define MSZ 1024
#define MAX_SPIKE 100000.0f

// Scratch: per batch, sorted spike times, gaps, and W-row byte offsets.
__device__ float g_xs[BATCH][KPAD];
__device__ float g_dx[BATCH][KPAD];
__device__ int   g_row[BATCH][KPAD];

// exact-rounding scalars so the replay is bit-identical to the mainloop
__device__ __forceinline__ float fadd_rn(float a, float b) {
    float d; asm("add.rn.f32 %0, %1, %2;" : "=f"(d) : "f"(a), "f"(b)); return d;
}
__device__ __forceinline__ float ffma_rn(float a, float b, float c) {
    float d; asm("fma.rn.f32 %0, %1, %2, %3;" : "=f"(d) : "f"(a), "f"(b), "f"(c)); return d;
}

// ---------------------------------------------------------------------------
// Kernel 1: per-batch bitonic sort of the 1024 X values (bias hardcoded at
// slot 0 since bias=1.0 <= min X; tie order provably irrelevant). Strides <=16
// in registers via shfl_xor; strides >=32 via shared memory.
// ---------------------------------------------------------------------------
__global__ void __launch_bounds__(1024) snn_sort_kernel(const float* __restrict__ X) {
    __shared__ unsigned long long sh[1024];
    __shared__ float sx[1025];
    const int b = blockIdx.x;
    const int t = threadIdx.x;

    unsigned long long v =
        ((unsigned long long)__float_as_uint(X[b * INSZ + t]) << 32) | (unsigned)t;

    #pragma unroll 1
    for (int size = 2; size <= 1024; size <<= 1) {
        #pragma unroll 1
        for (int stride = size >> 1; stride >= 32; stride >>= 1) {
            sh[t] = v;
            __syncthreads();
            const unsigned long long u = sh[t ^ stride];
            __syncthreads();
            const bool dir = (t & size) != 0;
            const bool keepmin = (((t & stride) == 0) != dir);
            v = keepmin ? (v < u ? v : u) : (v < u ? u : v);
        }
        const int s0 = (size >> 1) < 16 ? (size >> 1) : 16;
        #pragma unroll 1
        for (int stride = s0; stride >= 1; stride >>= 1) {
            const unsigned long long u = __shfl_xor_sync(0xffffffffu, v, stride);
            const bool dir = (t & size) != 0;
            const bool keepmin = (((t & stride) == 0) != dir);
            v = keepmin ? (v < u ? v : u) : (v < u ? u : v);
        }
    }

    sx[t + 1] = __uint_as_float((unsigned)(v >> 32));
    if (t == 0) sx[0] = 1.0f;
    __syncthreads();

    const int row = (int)(v & 0xffffffffu);
    const int s = t + 1;
    const float x  = sx[s];
    const float xn = (s == KSZ - 1) ? MAX_SPIKE : sx[s + 1];
    g_xs[b][s]  = x;
    g_dx[b][s]  = xn - x;
    g_row[b][s] = row * (MSZ * 4);
    if (t == 0) {
        g_xs[b][0]  = 1.0f;
        g_dx[b][0]  = sx[1] - 1.0f;
        g_row[b][0] = INSZ * (MSZ * 4);
    }
    if (t < KPAD - KSZ) {   // padding: w-row = bias row (all zeros), dx = 0
        g_xs[b][KSZ + t]  = MAX_SPIKE;
        g_dx[b][KSZ + t]  = 0.0f;
        g_row[b][KSZ + t] = INSZ * (MSZ * 4);
    }
}

// ---------------------------------------------------------------------------
// Kernel 2: margin scan, 1 column/thread, LDG register-ring prefetch.
//   cwp_k = cw_k - 1;  G_{k+1} = G_k + cwp_k * dx_k   (G_0 = -x_0 = -1)
// W is read straight from global (L2-resident, coalesced 128B/warp) into a
// 4-deep register ring of 8-element chunks, prefetched 3 chunks (24 elements)
// ahead — no smem staging, no per-chunk barriers. Mainloop per element:
// LDG + LDS(row) + LDS(dx, broadcast) + FADD + FFMA + FSETP.
// Per chunk: checkpoint (G, cwp, chunk#) while nd; the crossing chunk is
// replayed at the end (bit-exact rn ops):  T = x_kf - G_kf / cwp_kf.
// Grid: (MSZ/128, BATCH), 128 threads.
// ---------------------------------------------------------------------------
__global__ void __launch_bounds__(128) snn_scan_kernel(
    const float* __restrict__ W, float* __restrict__ out)
{
    __shared__ float s_dx[KPAD];
    __shared__ int   s_row[KPAD];

    const int b = blockIdx.y;
    const int t = threadIdx.x;
    const int mblock = blockIdx.x * 128;
    const char* Wcol = (const char*)W + (size_t)(mblock + t) * 4;

    for (int i = t; i < KPAD; i += 128) {
        s_dx[i]  = g_dx[b][i];
        s_row[i] = g_row[b][i];
    }
    __syncthreads();

    float wb[4][CHUNK];   // register ring

    // load one 8-element chunk of weights for this column
    auto load8 = [&](int c, float* buf) {
        const int kb = c * CHUNK;
        #pragma unroll
        for (int u = 0; u < CHUNK; u++)
            buf[u] = __ldg((const float*)(Wcol + s_row[kb + u]));
    };

    load8(0, wb[0]);
    load8(1, wb[1]);
    load8(2, wb[2]);

    float cwp = -1.0f;          // cw - THRESHOLD
    float G   = -1.0f;          // G_0 = -x_0, x_0 = bias = 1.0
    bool  nd  = true;           // not done (no crossing yet)
    float Gc  = -1.0f, cc = -1.0f;
    int   cb  = 0;

    #pragma unroll 4
    for (int c = 0; c < NCHUNK; c++) {
        // prefetch chunk c+3 (clamped; clamped writes hit never-consumed slots)
        const int pre = (c + 3 < NCHUNK) ? (c + 3) : (NCHUNK - 1);
        load8(pre, wb[(c + 3) & 3]);

        // per-chunk checkpoint while not done
        Gc = nd ? G   : Gc;
        cc = nd ? cwp : cc;
        cb = nd ? c   : cb;

        const float* buf = wb[c & 3];
        const int kb = c * CHUNK;
        #pragma unroll
        for (int u = 0; u < CHUNK; u++) {
            const float dx = s_dx[kb + u];
            cwp = fadd_rn(cwp, buf[u]);
            const float Gn = ffma_rn(cwp, dx, G);
            nd = nd && (Gn < 0.0f);
            G  = Gn;
        }
    }

    // replay the crossing chunk (bit-exact rn arithmetic, W L2/L1-hot)
    float res = MAX_SPIKE;
    if (!nd) {
        const int kb = cb * CHUNK;
        float Gr = Gc, cr = cc;
        bool found = false;
        #pragma unroll
        for (int j = 0; j < CHUNK; j++) {
            const float w  = __ldg((const float*)(Wcol + s_row[kb + j]));
            const float cn = fadd_rn(cr, w);
            const float Gn = ffma_rn(cn, s_dx[kb + j], Gr);
            if (!found && Gn >= 0.0f) {
                res = g_xs[b][kb + j] - Gr / cn;
                found = true;
            }
            cr = cn; Gr = Gn;
        }
    }
    out[(size_t)b * MSZ + mblock + t] = res;
}

// ---------------------------------------------------------------------------
extern "C" void kernel_launch(void* const* d_in, const int* in_sizes, int n_in,
                              void* d_out, int out_size) {
    const float* X = (const float*)d_in[0];   // [64, 1024] spike times
    const float* W = (const float*)d_in[1];   // [1025, 1024] weights
    float* out = (float*)d_out;               // [64, 1024]

    snn_sort_kernel<<<BATCH, 1024>>>(X);
    snn_scan_kernel<<<dim3(MSZ / 128, BATCH), 128>>>(W, out);
}

// round 16
// speedup vs baseline: 1.3916x; 1.0483x over previous
#include <cuda_runtime.h>
#include <stdint.h>

#define BATCH 64
#define INSZ 1024
#define KSZ 1025          // inputs + bias neuron (bias always first: t=1.0 <= X)
#define KPAD 1056         // 132 chunks of 8 (padding: w=0, dx=0 -> provable no-op)
#define CHUNK 8
#define NCHUNK (KPAD / CHUNK)   // 132
#define MSZ 1024
#define MAX_SPIKE 100000.0f

// Scratch: per batch, sorted spike times and fused (dx, row-byte-offset) pairs.
__device__ float  g_xs[BATCH][KPAD];
__device__ float2 g_pair[BATCH][KPAD];   // .x = dx_k, .y = int_bits(row_k * 4096)

// exact-rounding scalars so the replay is bit-identical to the mainloop
__device__ __forceinline__ float fadd_rn(float a, float b) {
    float d; asm("add.rn.f32 %0, %1, %2;" : "=f"(d) : "f"(a), "f"(b)); return d;
}
__device__ __forceinline__ float ffma_rn(float a, float b, float c) {
    float d; asm("fma.rn.f32 %0, %1, %2, %3;" : "=f"(d) : "f"(a), "f"(b), "f"(c)); return d;
}

// ---------------------------------------------------------------------------
// Kernel 1: per-batch bitonic sort of the 1024 X values (bias hardcoded at
// slot 0 since bias=1.0 <= min X; tie order provably irrelevant). Strides <=16
// in registers via shfl_xor; strides >=32 via shared memory.
// ---------------------------------------------------------------------------
__global__ void __launch_bounds__(1024) snn_sort_kernel(const float* __restrict__ X) {
    __shared__ unsigned long long sh[1024];
    __shared__ float sx[1025];
    const int b = blockIdx.x;
    const int t = threadIdx.x;

    unsigned long long v =
        ((unsigned long long)__float_as_uint(X[b * INSZ + t]) << 32) | (unsigned)t;

    #pragma unroll 1
    for (int size = 2; size <= 1024; size <<= 1) {
        #pragma unroll 1
        for (int stride = size >> 1; stride >= 32; stride >>= 1) {
            sh[t] = v;
            __syncthreads();
            const unsigned long long u = sh[t ^ stride];
            __syncthreads();
            const bool dir = (t & size) != 0;
            const bool keepmin = (((t & stride) == 0) != dir);
            v = keepmin ? (v < u ? v : u) : (v < u ? u : v);
        }
        const int s0 = (size >> 1) < 16 ? (size >> 1) : 16;
        #pragma unroll 1
        for (int stride = s0; stride >= 1; stride >>= 1) {
            const unsigned long long u = __shfl_xor_sync(0xffffffffu, v, stride);
            const bool dir = (t & size) != 0;
            const bool keepmin = (((t & stride) == 0) != dir);
            v = keepmin ? (v < u ? v : u) : (v < u ? u : v);
        }
    }

    sx[t + 1] = __uint_as_float((unsigned)(v >> 32));
    if (t == 0) sx[0] = 1.0f;
    __syncthreads();

    const int row = (int)(v & 0xffffffffu);
    const int s = t + 1;
    const float x  = sx[s];
    const float xn = (s == KSZ - 1) ? MAX_SPIKE : sx[s + 1];
    g_xs[b][s]   = x;
    g_pair[b][s] = make_float2(xn - x, __int_as_float(row * (MSZ * 4)));
    if (t == 0) {
        g_xs[b][0]   = 1.0f;
        g_pair[b][0] = make_float2(sx[1] - 1.0f, __int_as_float(INSZ * (MSZ * 4)));
    }
    if (t < KPAD - KSZ) {   // padding: w-row = bias row (all zeros), dx = 0
        g_xs[b][KSZ + t]   = MAX_SPIKE;
        g_pair[b][KSZ + t] = make_float2(0.0f, __int_as_float(INSZ * (MSZ * 4)));
    }
}

// ---------------------------------------------------------------------------
// Kernel 2: margin scan, 1 column/thread, LDG+dx register-ring prefetch.
//   cwp_k = cw_k - 1;  G_{k+1} = G_k + cwp_k * dx_k   (G_0 = -x_0 = -1)
// Prefetch (3 chunks = 24 elts ahead): LDS.64 (dx,row) + IMAD.WIDE + LDG,
// stashing BOTH w and dx in register rings. Consume per element is pure math:
// FADD + FFMA + FSETP — no memory ops on the critical stream.
// Per chunk: checkpoint (G, cwp, chunk#) while nd; the crossing chunk is
// replayed at the end (bit-exact rn ops):  T = x_kf - G_kf / cwp_kf.
// Grid: (MSZ/128, BATCH), 128 threads.
// ---------------------------------------------------------------------------
__global__ void __launch_bounds__(128) snn_scan_kernel(
    const float* __restrict__ W, float* __restrict__ out)
{
    __shared__ float2 s_pair[KPAD];

    const int b = blockIdx.y;
    const int t = threadIdx.x;
    const int mblock = blockIdx.x * 128;
    const char* Wcol = (const char*)W + (size_t)(mblock + t) * 4;

    for (int i = t; i < KPAD; i += 128)
        s_pair[i] = g_pair[b][i];
    __syncthreads();

    float wb[4][CHUNK];    // weight ring
    float db[4][CHUNK];    // dx ring

    // prefetch one 8-element chunk: weights via LDG, dx into registers
    auto load8 = [&](int c, float* wdst, float* ddst) {
        const int kb = c * CHUNK;
        #pragma unroll
        for (int u = 0; u < CHUNK; u++) {
            const float2 p = s_pair[kb + u];
            ddst[u] = p.x;
            wdst[u] = __ldg((const float*)(Wcol + __float_as_int(p.y)));
        }
    };

    load8(0, wb[0], db[0]);
    load8(1, wb[1], db[1]);
    load8(2, wb[2], db[2]);

    float cwp = -1.0f;          // cw - THRESHOLD
    float G   = -1.0f;          // G_0 = -x_0, x_0 = bias = 1.0
    bool  nd  = true;           // not done (no crossing yet)
    float Gc  = -1.0f, cc = -1.0f;
    int   cb  = 0;

    #pragma unroll 4
    for (int c = 0; c < NCHUNK; c++) {
        // prefetch chunk c+3 (clamped; clamped writes hit never-consumed slots)
        const int pre = (c + 3 < NCHUNK) ? (c + 3) : (NCHUNK - 1);
        load8(pre, wb[(c + 3) & 3], db[(c + 3) & 3]);

        // per-chunk checkpoint while not done
        Gc = nd ? G   : Gc;
        cc = nd ? cwp : cc;
        cb = nd ? c   : cb;

        const float* wv = wb[c & 3];
        const float* dv = db[c & 3];
        #pragma unroll
        for (int u = 0; u < CHUNK; u++) {
            cwp = fadd_rn(cwp, wv[u]);
            const float Gn = ffma_rn(cwp, dv[u], G);
            nd = nd && (Gn < 0.0f);
            G  = Gn;
        }
    }

    // replay the crossing chunk (bit-exact rn arithmetic, W L2/L1-hot)
    float res = MAX_SPIKE;
    if (!nd) {
        const int kb = cb * CHUNK;
        float Gr = Gc, cr = cc;
        bool found = false;
        #pragma unroll
        for (int j = 0; j < CHUNK; j++) {
            const float2 p = s_pair[kb + j];
            const float w  = __ldg((const float*)(Wcol + __float_as_int(p.y)));
            const float cn = fadd_rn(cr, w);
            const float Gn = ffma_rn(cn, p.x, Gr);
            if (!found && Gn >= 0.0f) {
                res = g_xs[b][kb + j] - Gr / cn;
                found = true;
            }
            cr = cn; Gr = Gn;
        }
    }
    out[(size_t)b * MSZ + mblock + t] = res;
}

// ---------------------------------------------------------------------------
extern "C" void kernel_launch(void* const* d_in, const int* in_sizes, int n_in,
                              void* d_out, int out_size) {
    const float* X = (const float*)d_in[0];   // [64, 1024] spike times
    const float* W = (const float*)d_in[1];   // [1025, 1024] weights
    float* out = (float*)d_out;               // [64, 1024]

    snn_sort_kernel<<<BATCH, 1024>>>(X);
    snn_scan_kernel<<<dim3(MSZ / 128, BATCH), 128>>>(W, out);
}